// round 10
// baseline (speedup 1.0000x reference)
#include <cuda_runtime.h>
#include <cuda_fp16.h>
#include <math.h>

#define N_NODES 100000
#define MAX_E   3200000
#define F_IN    128
#define F_HID   24
#define F_OUT   16
#define HID_PAD 32         // padded half-row stride for hs1 (64B lines)
#define CAP     64         // fixed bucket capacity per node (Poisson(32) max ~62)
#define PADI    32         // cursor stride in ints = 128B (kills LTS line serialization)

// ---------------- scratch (device globals; no allocation allowed) ------------
__device__ int    g_is64;
__device__ int    g_novf;
__device__ int    g_cursor[N_NODES * PADI];   // 12.8MB, one counter per 128B line
__device__ float  g_dinv[N_NODES];
__device__ int    g_csr[N_NODES * CAP];       // 25.6MB fixed buckets
__device__ int2   g_ovf[MAX_E];               // overflow (dst,src); worst-case sized
__device__ __half g_hs1h[N_NODES * HID_PAD];  // (x@W1)*dinv, fp16, 64B rows
__device__ __half g_hs2h[N_NODES * F_OUT];    // (relu-l1 @ W2)*dinv, fp16, 32B rows

// dtype probe: int64 node ids < 2^31 -> odd 32-bit words all zero.
__device__ __forceinline__ int probe_is64(const void* ei) {
    const unsigned int* w = (const unsigned int*)ei;
    unsigned acc = 0;
    #pragma unroll
    for (int i = 0; i < 16; i++) acc |= w[2 * i + 1];
    return acc == 0u;
}

__device__ __forceinline__ int edge_at(const void* ei, int is64, long long idx) {
    return is64 ? (int)((const long long*)ei)[idx] : ((const int*)ei)[idx];
}

// ---------------- prep: zero cursors, reset overflow, probe dtype ------------
__global__ void k_prep(const void* __restrict__ ei) {
    int n = blockIdx.x * blockDim.x + threadIdx.x;
    if (n < N_NODES) g_cursor[n * PADI] = 0;
    if (n == 0) {
        g_novf = 0;
        g_is64 = probe_is64(ei);
    }
}

// ---------------- single-pass bucket fill: 2 edges/thread, vectorized --------
__global__ void k_fill(const void* __restrict__ ei, int E) {
    __shared__ int sIs64;
    if (threadIdx.x == 0) sIs64 = g_is64;
    __syncthreads();
    int t = blockIdx.x * blockDim.x + threadIdx.x;
    int Ev = E & ~1;
    int e = t * 2;
    if (e < Ev) {
        int d0, d1, s0, s1;
        if (sIs64) {
            longlong2 d = ((const longlong2*)ei)[t];
            longlong2 s = ((const longlong2*)ei)[(E >> 1) + t];   // E even in practice
            d0 = (int)d.x; d1 = (int)d.y; s0 = (int)s.x; s1 = (int)s.y;
        } else {
            int2 d = ((const int2*)ei)[t];
            int2 s = ((const int2*)ei)[(E >> 1) + t];
            d0 = d.x; d1 = d.y; s0 = s.x; s1 = s.y;
        }
        int c0 = atomicAdd(&g_cursor[d0 * PADI], 1);
        if (c0 < CAP) g_csr[(d0 << 6) + c0] = s0;
        else { int o = atomicAdd(&g_novf, 1); g_ovf[o] = make_int2(d0, s0); }
        int c1 = atomicAdd(&g_cursor[d1 * PADI], 1);
        if (c1 < CAP) g_csr[(d1 << 6) + c1] = s1;
        else { int o = atomicAdd(&g_novf, 1); g_ovf[o] = make_int2(d1, s1); }
    }
    if (t == 0 && (E & 1)) {               // scalar tail for odd E
        int is64 = g_is64;
        int dst = edge_at(ei, is64, E - 1);
        int src = edge_at(ei, is64, 2LL * E - 1);
        int c = atomicAdd(&g_cursor[dst * PADI], 1);
        if (c < CAP) g_csr[(dst << 6) + c] = src;
        else { int o = atomicAdd(&g_novf, 1); g_ovf[o] = make_int2(dst, src); }
    }
}

// ---------------- GEMM1: hs1h = fp16((x @ W1) * dinv); computes dinv ---------
__global__ __launch_bounds__(256) void k_gemm1(const float* __restrict__ x,
                                               const float* __restrict__ W1) {
    __shared__ float Ws[F_IN * F_HID];                   // 12 KB
    __shared__ __align__(16) float xs[32 * F_IN];        // 16 KB
    int tid = threadIdx.x;
    for (int i = tid; i < F_IN * F_HID; i += 256) Ws[i] = W1[i];

    int base = blockIdx.x * 32;                          // 3125 * 32 = 100000
    const float4* xv = (const float4*)(x + (size_t)base * F_IN);
    float4* xsv = (float4*)xs;
    for (int i = tid; i < 32 * (F_IN / 4); i += 256) xsv[i] = xv[i];
    __syncthreads();

    int nloc = tid >> 3;                                 // 0..31
    int l = tid & 7;                                     // 0..7, 3 outputs each
    int node = base + nloc;

    float a0 = 0.f, a1 = 0.f, a2 = 0.f;
    const float* xr = xs + nloc * F_IN;
    #pragma unroll
    for (int k = 0; k < F_IN; k++) {
        float xk = xr[k];
        a0 = fmaf(xk, Ws[k * F_HID + l * 3 + 0], a0);
        a1 = fmaf(xk, Ws[k * F_HID + l * 3 + 1], a1);
        a2 = fmaf(xk, Ws[k * F_HID + l * 3 + 2], a2);
    }
    int deg = g_cursor[node * PADI];                     // total in-degree
    float dv = rsqrtf((float)(deg + 1));                 // +1 self-loop
    if (l == 0) g_dinv[node] = dv;
    __half* o = g_hs1h + (size_t)node * HID_PAD + l * 3;
    o[0] = __float2half_rn(a0 * dv);
    o[1] = __float2half_rn(a1 * dv);
    o[2] = __float2half_rn(a2 * dv);
    if (l == 7) {                                        // zero pad halfs [24..32)
        uint4 z = make_uint4(0u, 0u, 0u, 0u);
        *(uint4*)(g_hs1h + (size_t)node * HID_PAD + 24) = z;
    }
}

// fp32 accumulate of one fp16x8 vector
__device__ __forceinline__ void add8(float* acc, uint4 v) {
    __half2* hp = (__half2*)&v;
    #pragma unroll
    for (int c = 0; c < 4; c++) {
        float2 f = __half22float2(hp[c]);
        acc[2*c]   += f.x;
        acc[2*c+1] += f.y;
    }
}

// pairwise: fp16 add two vectors, convert pair-sum once, fp32 accumulate
__device__ __forceinline__ void add8p(float* acc, uint4 a, uint4 b) {
    __half2* pa = (__half2*)&a;
    __half2* pb = (__half2*)&b;
    #pragma unroll
    for (int c = 0; c < 4; c++) {
        float2 f = __half22float2(__hadd2(pa[c], pb[c]));
        acc[2*c]   += f.x;
        acc[2*c+1] += f.y;
    }
}

// ---------------- layer1 gather: 4 lanes/node, vector index loads + shfl -----
__global__ __launch_bounds__(256) void k_gather1(const float* __restrict__ b1,
                                                 const float* __restrict__ W2) {
    __shared__ float W2s[F_HID * F_OUT];
    __shared__ float b1s[F_HID];
    int tid = threadIdx.x;
    for (int i = tid; i < F_HID * F_OUT; i += 256) W2s[i] = W2[i];
    if (tid < F_HID) b1s[tid] = b1[tid];
    __syncthreads();

    int lane = tid & 31;
    int l = lane & 3;
    int gbase = lane & ~3;                    // first lane of this 4-lane node group
    unsigned gmask = 0xFu << gbase;           // group member mask (converged subgroup)
    int node = blockIdx.x * 64 + (tid >> 2);
    int nc = (node < N_NODES) ? node : (N_NODES - 1);

    const uint4* base = (const uint4*)g_hs1h;
    float acc[8];
    {
        uint4 sv = base[(size_t)nc * 4 + l];     // self-loop term
        __half2* hp = (__half2*)&sv;
        #pragma unroll
        for (int c = 0; c < 4; c++) {
            float2 f = __half22float2(hp[c]);
            acc[2*c] = f.x; acc[2*c+1] = f.y;
        }
    }
    int cnt = g_cursor[nc * PADI];
    int deg = cnt < CAP ? cnt : CAP;
    int s = nc << 6, e = s + deg;
    int i = s;
    for (; i + 7 < e; i += 8) {
        // one LDG.64 per lane covers all 8 indices of the group
        int2 ip = ((const int2*)(g_csr + i))[l];    // lane l: indices i+2l, i+2l+1
        #pragma unroll
        for (int j = 0; j < 4; j++) {
            int a = __shfl_sync(gmask, ip.x, gbase + j);
            int b = __shfl_sync(gmask, ip.y, gbase + j);
            uint4 va = base[(size_t)a * 4 + l];
            uint4 vb = base[(size_t)b * 4 + l];
            add8p(acc, va, vb);
        }
    }
    for (; i + 1 < e; i += 2) {
        add8p(acc, base[(size_t)g_csr[i] * 4 + l], base[(size_t)g_csr[i+1] * 4 + l]);
    }
    if (i < e) add8(acc, base[(size_t)g_csr[i] * 4 + l]);

    int novf = g_novf;                     // normally 0; correctness fallback
    for (int k = 0; k < novf; k++) {
        int2 p = g_ovf[k];
        if (p.x == nc) add8(acc, base[(size_t)p.y * 4 + l]);
    }

    float dv = g_dinv[nc];
    float h[8];
    if (l < 3) {
        #pragma unroll
        for (int k = 0; k < 8; k++)
            h[k] = fmaxf(fmaf(dv, acc[k], b1s[l * 8 + k]), 0.f);
    } else {
        #pragma unroll
        for (int k = 0; k < 8; k++) h[k] = 0.f;
    }

    // GEMM2 epilogue: executed by ALL lanes (converged) — full-warp shfl is safe
    float o0 = 0.f, o1 = 0.f, o2 = 0.f, o3 = 0.f;
    #pragma unroll
    for (int j = 0; j < F_HID; j++) {
        float hj = __shfl_sync(0xffffffffu, h[j & 7], gbase + (j >> 3));
        o0 = fmaf(hj, W2s[j * F_OUT + l*4 + 0], o0);
        o1 = fmaf(hj, W2s[j * F_OUT + l*4 + 1], o1);
        o2 = fmaf(hj, W2s[j * F_OUT + l*4 + 2], o2);
        o3 = fmaf(hj, W2s[j * F_OUT + l*4 + 3], o3);
    }
    if (node < N_NODES) {
        __half2* op = (__half2*)(g_hs2h + (size_t)node * F_OUT + l * 4);
        op[0] = __floats2half2_rn(o0 * dv, o1 * dv);
        op[1] = __floats2half2_rn(o2 * dv, o3 * dv);
    }
}

// ---------------- layer2 gather: 2 lanes/node, vector index loads + shfl -----
__global__ __launch_bounds__(256) void k_gather2(const float* __restrict__ b2,
                                                 float* __restrict__ out) {
    __shared__ float b2s[F_OUT];
    if (threadIdx.x < F_OUT) b2s[threadIdx.x] = b2[threadIdx.x];
    __syncthreads();

    int tid = threadIdx.x;
    int lane = tid & 31;
    int l = lane & 1;
    int gbase = lane & ~1;
    unsigned gmask = 0x3u << gbase;        // pair member mask
    int node = blockIdx.x * 128 + (tid >> 1);
    int nc = (node < N_NODES) ? node : (N_NODES - 1);

    const uint4* base = (const uint4*)g_hs2h;
    float acc[8];
    {
        uint4 sv = base[(size_t)nc * 2 + l];
        __half2* hp = (__half2*)&sv;
        #pragma unroll
        for (int c = 0; c < 4; c++) {
            float2 f = __half22float2(hp[c]);
            acc[2*c] = f.x; acc[2*c+1] = f.y;
        }
    }
    int cnt = g_cursor[nc * PADI];
    int deg = cnt < CAP ? cnt : CAP;
    int s = nc << 6, e = s + deg;
    int i = s;
    for (; i + 7 < e; i += 8) {
        // one LDG.128 per lane covers all 8 indices of the pair
        uint4 ipk = ((const uint4*)(g_csr + i))[l];   // lane0: i..i+3, lane1: i+4..i+7
        #pragma unroll
        for (int j = 0; j < 4; j++) {
            int srcl = gbase + (j >> 1);
            int a = __shfl_sync(gmask, (int)((j & 1) ? ipk.z : ipk.x), srcl);
            int b = __shfl_sync(gmask, (int)((j & 1) ? ipk.w : ipk.y), srcl);
            uint4 va = base[(size_t)a * 2 + l];
            uint4 vb = base[(size_t)b * 2 + l];
            add8p(acc, va, vb);
        }
    }
    for (; i + 1 < e; i += 2) {
        add8p(acc, base[(size_t)g_csr[i] * 2 + l], base[(size_t)g_csr[i+1] * 2 + l]);
    }
    if (i < e) add8(acc, base[(size_t)g_csr[i] * 2 + l]);

    int novf = g_novf;                     // normally 0; correctness fallback
    for (int k = 0; k < novf; k++) {
        int2 p = g_ovf[k];
        if (p.x == nc) add8(acc, base[(size_t)p.y * 2 + l]);
    }

    float dv = g_dinv[nc];
    float z[8];
    #pragma unroll
    for (int k = 0; k < 8; k++) z[k] = fmaf(dv, acc[k], b2s[l * 8 + k]);

    // converged epilogue: full-warp shuffles safe
    float m = z[0];
    #pragma unroll
    for (int k = 1; k < 8; k++) m = fmaxf(m, z[k]);
    m = fmaxf(m, __shfl_xor_sync(0xffffffffu, m, 1));
    float sum = 0.f;
    #pragma unroll
    for (int k = 0; k < 8; k++) sum += __expf(z[k] - m);
    sum += __shfl_xor_sync(0xffffffffu, sum, 1);
    float lse = m + __logf(sum);

    if (node < N_NODES) {
        float4* outp = (float4*)out + (size_t)node * 4 + l * 2;
        float4 w0, w1;
        w0.x = z[0] - lse; w0.y = z[1] - lse; w0.z = z[2] - lse; w0.w = z[3] - lse;
        w1.x = z[4] - lse; w1.y = z[5] - lse; w1.z = z[6] - lse; w1.w = z[7] - lse;
        outp[0] = w0; outp[1] = w1;
    }
}

// ---------------- launch ------------------------------------------------------
extern "C" void kernel_launch(void* const* d_in, const int* in_sizes, int n_in,
                              void* d_out, int out_size) {
    const float* x  = (const float*)d_in[0];
    const void*  ei = d_in[1];
    const float* W1 = (const float*)d_in[2];
    const float* b1 = (const float*)d_in[3];
    const float* W2 = (const float*)d_in[4];
    const float* b2 = (const float*)d_in[5];
    float* out = (float*)d_out;

    int E = in_sizes[1] / 2;
    if (E > MAX_E) E = MAX_E;

    const int NB = (N_NODES + 255) / 256;     // 391
    const int E2 = (E / 2 + 255) / 256;       // 2 edges/thread blocks

    k_prep<<<NB, 256>>>(ei);
    k_fill<<<E2, 256>>>(ei, E);
    k_gemm1<<<N_NODES / 32, 256>>>(x, W1);
    k_gather1<<<(N_NODES + 63) / 64, 256>>>(b1, W2);
    k_gather2<<<(N_NODES + 127) / 128, 256>>>(b2, out);
}

// round 11
// speedup vs baseline: 1.4473x; 1.4473x over previous
#include <cuda_runtime.h>
#include <cuda_fp16.h>
#include <math.h>

#define N_NODES 100000
#define MAX_E   3200000
#define F_IN    128
#define F_HID   24
#define F_OUT   16
#define HID_PAD 32         // padded half-row stride for hs1 (64B lines)
#define CAP     64         // fixed bucket capacity per node (Poisson(32) max ~62)
#define PADI    32         // cursor stride in ints = 128B (kills LTS line serialization)

// ---------------- scratch (device globals; no allocation allowed) ------------
// Invariant: g_cursor is all-zero at kernel_launch entry (zero-init at load;
// k_gather2 re-zeroes after final read). g_novf likewise reset by k_gemm1.
__device__ int    g_novf;
__device__ int    g_novf2;
__device__ int    g_cursor[N_NODES * PADI];   // 12.8MB, one counter per 128B line
__device__ float  g_dinv[N_NODES];
__device__ int    g_csr[N_NODES * CAP];       // 25.6MB fixed buckets
__device__ int2   g_ovf[MAX_E];               // overflow (dst,src); worst-case sized
__device__ __half g_hs1h[N_NODES * HID_PAD];  // (x@W1)*dinv, fp16, 64B rows
__device__ __half g_hs2h[N_NODES * F_OUT];    // (relu-l1 @ W2)*dinv, fp16, 32B rows

// dtype probe: int64 node ids < 2^31 -> odd 32-bit words all zero.
__device__ __forceinline__ int probe_is64(const void* ei) {
    const unsigned int* w = (const unsigned int*)ei;
    unsigned acc = 0;
    #pragma unroll
    for (int i = 0; i < 16; i++) acc |= w[2 * i + 1];
    return acc == 0u;
}

__device__ __forceinline__ int edge_at(const void* ei, int is64, long long idx) {
    return is64 ? (int)((const long long*)ei)[idx] : ((const int*)ei)[idx];
}

// ---------------- single-pass bucket fill: 2 edges/thread, vectorized --------
__global__ void k_fill(const void* __restrict__ ei, int E) {
    __shared__ int sIs64;
    if (threadIdx.x == 0) sIs64 = probe_is64(ei);
    __syncthreads();
    int t = blockIdx.x * blockDim.x + threadIdx.x;
    int Ev = E & ~1;
    int e = t * 2;
    if (e < Ev) {
        int d0, d1, s0, s1;
        if (sIs64) {
            longlong2 d = ((const longlong2*)ei)[t];
            longlong2 s = ((const longlong2*)ei)[(E >> 1) + t];   // E even in practice
            d0 = (int)d.x; d1 = (int)d.y; s0 = (int)s.x; s1 = (int)s.y;
        } else {
            int2 d = ((const int2*)ei)[t];
            int2 s = ((const int2*)ei)[(E >> 1) + t];
            d0 = d.x; d1 = d.y; s0 = s.x; s1 = s.y;
        }
        int c0 = atomicAdd(&g_cursor[d0 * PADI], 1);
        if (c0 < CAP) g_csr[(d0 << 6) + c0] = s0;
        else { int o = atomicAdd(&g_novf, 1); g_ovf[o] = make_int2(d0, s0); }
        int c1 = atomicAdd(&g_cursor[d1 * PADI], 1);
        if (c1 < CAP) g_csr[(d1 << 6) + c1] = s1;
        else { int o = atomicAdd(&g_novf, 1); g_ovf[o] = make_int2(d1, s1); }
    }
    if (t == 0 && (E & 1)) {               // scalar tail for odd E
        int is64 = sIs64;
        int dst = edge_at(ei, is64, E - 1);
        int src = edge_at(ei, is64, 2LL * E - 1);
        int c = atomicAdd(&g_cursor[dst * PADI], 1);
        if (c < CAP) g_csr[(dst << 6) + c] = src;
        else { int o = atomicAdd(&g_novf, 1); g_ovf[o] = make_int2(dst, src); }
    }
}

// ---------------- GEMM1: hs1h = fp16((x @ W1) * dinv); computes dinv ---------
// Also latches g_novf -> g_novf2 and resets g_novf (single thread; runs after
// k_fill, before the gathers, so ordering is by kernel boundaries).
__global__ __launch_bounds__(256) void k_gemm1(const float* __restrict__ x,
                                               const float* __restrict__ W1) {
    __shared__ float Ws[F_IN * F_HID];                   // 12 KB
    __shared__ __align__(16) float xs[32 * F_IN];        // 16 KB
    int tid = threadIdx.x;
    if (blockIdx.x == 0 && tid == 0) {
        g_novf2 = g_novf;
        g_novf = 0;
    }
    for (int i = tid; i < F_IN * F_HID; i += 256) Ws[i] = W1[i];

    int base = blockIdx.x * 32;                          // 3125 * 32 = 100000
    const float4* xv = (const float4*)(x + (size_t)base * F_IN);
    float4* xsv = (float4*)xs;
    for (int i = tid; i < 32 * (F_IN / 4); i += 256) xsv[i] = xv[i];
    __syncthreads();

    int nloc = tid >> 3;                                 // 0..31
    int l = tid & 7;                                     // 0..7, 3 outputs each
    int node = base + nloc;

    float a0 = 0.f, a1 = 0.f, a2 = 0.f;
    const float* xr = xs + nloc * F_IN;
    #pragma unroll
    for (int k = 0; k < F_IN; k++) {
        float xk = xr[k];
        a0 = fmaf(xk, Ws[k * F_HID + l * 3 + 0], a0);
        a1 = fmaf(xk, Ws[k * F_HID + l * 3 + 1], a1);
        a2 = fmaf(xk, Ws[k * F_HID + l * 3 + 2], a2);
    }
    int deg = g_cursor[node * PADI];                     // total in-degree
    float dv = rsqrtf((float)(deg + 1));                 // +1 self-loop
    if (l == 0) g_dinv[node] = dv;
    __half* o = g_hs1h + (size_t)node * HID_PAD + l * 3;
    o[0] = __float2half_rn(a0 * dv);
    o[1] = __float2half_rn(a1 * dv);
    o[2] = __float2half_rn(a2 * dv);
    if (l == 7) {                                        // zero pad halfs [24..32)
        uint4 z = make_uint4(0u, 0u, 0u, 0u);
        *(uint4*)(g_hs1h + (size_t)node * HID_PAD + 24) = z;
    }
}

// fp32 accumulate of one fp16x8 vector
__device__ __forceinline__ void add8(float* acc, uint4 v) {
    __half2* hp = (__half2*)&v;
    #pragma unroll
    for (int c = 0; c < 4; c++) {
        float2 f = __half22float2(hp[c]);
        acc[2*c]   += f.x;
        acc[2*c+1] += f.y;
    }
}

// pairwise: fp16 add two vectors, convert pair-sum once, fp32 accumulate
__device__ __forceinline__ void add8p(float* acc, uint4 a, uint4 b) {
    __half2* pa = (__half2*)&a;
    __half2* pb = (__half2*)&b;
    #pragma unroll
    for (int c = 0; c < 4; c++) {
        float2 f = __half22float2(__hadd2(pa[c], pb[c]));
        acc[2*c]   += f.x;
        acc[2*c+1] += f.y;
    }
}

// ---------------- layer1 gather (4 lanes/node, unroll 8) + relu + GEMM2 ------
__global__ __launch_bounds__(256) void k_gather1(const float* __restrict__ b1,
                                                 const float* __restrict__ W2) {
    __shared__ float W2s[F_HID * F_OUT];
    __shared__ float b1s[F_HID];
    int tid = threadIdx.x;
    for (int i = tid; i < F_HID * F_OUT; i += 256) W2s[i] = W2[i];
    if (tid < F_HID) b1s[tid] = b1[tid];
    __syncthreads();

    int lane = tid & 31;
    int l = lane & 3;
    int node = blockIdx.x * 64 + (tid >> 2);
    int nc = (node < N_NODES) ? node : (N_NODES - 1);

    const uint4* base = (const uint4*)g_hs1h;
    float acc[8];
    {
        uint4 sv = base[(size_t)nc * 4 + l];     // self-loop term
        __half2* hp = (__half2*)&sv;
        #pragma unroll
        for (int c = 0; c < 4; c++) {
            float2 f = __half22float2(hp[c]);
            acc[2*c] = f.x; acc[2*c+1] = f.y;
        }
    }
    int cnt = g_cursor[nc * PADI];
    int deg = cnt < CAP ? cnt : CAP;
    int s = nc << 6, e = s + deg;
    int i = s;
    for (; i + 7 < e; i += 8) {            // 8 gathers in flight per lane
        uint4 v0 = base[(size_t)g_csr[i]   * 4 + l];
        uint4 v1 = base[(size_t)g_csr[i+1] * 4 + l];
        uint4 v2 = base[(size_t)g_csr[i+2] * 4 + l];
        uint4 v3 = base[(size_t)g_csr[i+3] * 4 + l];
        uint4 v4 = base[(size_t)g_csr[i+4] * 4 + l];
        uint4 v5 = base[(size_t)g_csr[i+5] * 4 + l];
        uint4 v6 = base[(size_t)g_csr[i+6] * 4 + l];
        uint4 v7 = base[(size_t)g_csr[i+7] * 4 + l];
        add8p(acc, v0, v1); add8p(acc, v2, v3);
        add8p(acc, v4, v5); add8p(acc, v6, v7);
    }
    if (i + 3 < e) {
        uint4 v0 = base[(size_t)g_csr[i]   * 4 + l];
        uint4 v1 = base[(size_t)g_csr[i+1] * 4 + l];
        uint4 v2 = base[(size_t)g_csr[i+2] * 4 + l];
        uint4 v3 = base[(size_t)g_csr[i+3] * 4 + l];
        add8p(acc, v0, v1); add8p(acc, v2, v3);
        i += 4;
    }
    if (i + 1 < e) {
        add8p(acc, base[(size_t)g_csr[i] * 4 + l], base[(size_t)g_csr[i+1] * 4 + l]);
        i += 2;
    }
    if (i < e) add8(acc, base[(size_t)g_csr[i] * 4 + l]);

    int novf = g_novf2;                    // normally 0; correctness fallback
    for (int k = 0; k < novf; k++) {
        int2 p = g_ovf[k];
        if (p.x == nc) add8(acc, base[(size_t)p.y * 4 + l]);
    }

    float dv = g_dinv[nc];
    float h[8];
    if (l < 3) {
        #pragma unroll
        for (int k = 0; k < 8; k++)
            h[k] = fmaxf(fmaf(dv, acc[k], b1s[l * 8 + k]), 0.f);
    } else {
        #pragma unroll
        for (int k = 0; k < 8; k++) h[k] = 0.f;
    }

    float o0 = 0.f, o1 = 0.f, o2 = 0.f, o3 = 0.f;
    int gbase = lane & ~3;
    #pragma unroll
    for (int j = 0; j < F_HID; j++) {
        float hj = __shfl_sync(0xffffffffu, h[j & 7], gbase + (j >> 3));
        o0 = fmaf(hj, W2s[j * F_OUT + l*4 + 0], o0);
        o1 = fmaf(hj, W2s[j * F_OUT + l*4 + 1], o1);
        o2 = fmaf(hj, W2s[j * F_OUT + l*4 + 2], o2);
        o3 = fmaf(hj, W2s[j * F_OUT + l*4 + 3], o3);
    }
    if (node < N_NODES) {
        __half2* op = (__half2*)(g_hs2h + (size_t)node * F_OUT + l * 4);
        op[0] = __floats2half2_rn(o0 * dv, o1 * dv);
        op[1] = __floats2half2_rn(o2 * dv, o3 * dv);
    }
}

// ---------------- layer2 gather (2 lanes/node, unroll 8) + log_softmax -------
// Also re-zeroes each node's cursor after the final read (leaves the invariant
// for the next kernel_launch call / graph replay).
__global__ __launch_bounds__(256) void k_gather2(const float* __restrict__ b2,
                                                 float* __restrict__ out) {
    __shared__ float b2s[F_OUT];
    if (threadIdx.x < F_OUT) b2s[threadIdx.x] = b2[threadIdx.x];
    __syncthreads();

    int tid = threadIdx.x;
    int lane = tid & 31;
    int l = lane & 1;
    int node = blockIdx.x * 128 + (tid >> 1);
    int nc = (node < N_NODES) ? node : (N_NODES - 1);

    const uint4* base = (const uint4*)g_hs2h;
    float acc[8];
    {
        uint4 sv = base[(size_t)nc * 2 + l];
        __half2* hp = (__half2*)&sv;
        #pragma unroll
        for (int c = 0; c < 4; c++) {
            float2 f = __half22float2(hp[c]);
            acc[2*c] = f.x; acc[2*c+1] = f.y;
        }
    }
    int cnt = g_cursor[nc * PADI];
    if (l == 0 && node < N_NODES) g_cursor[nc * PADI] = 0;   // reset for next call
    int deg = cnt < CAP ? cnt : CAP;
    int s = nc << 6, e = s + deg;
    int i = s;
    for (; i + 7 < e; i += 8) {
        uint4 v0 = base[(size_t)g_csr[i]   * 2 + l];
        uint4 v1 = base[(size_t)g_csr[i+1] * 2 + l];
        uint4 v2 = base[(size_t)g_csr[i+2] * 2 + l];
        uint4 v3 = base[(size_t)g_csr[i+3] * 2 + l];
        uint4 v4 = base[(size_t)g_csr[i+4] * 2 + l];
        uint4 v5 = base[(size_t)g_csr[i+5] * 2 + l];
        uint4 v6 = base[(size_t)g_csr[i+6] * 2 + l];
        uint4 v7 = base[(size_t)g_csr[i+7] * 2 + l];
        add8p(acc, v0, v1); add8p(acc, v2, v3);
        add8p(acc, v4, v5); add8p(acc, v6, v7);
    }
    if (i + 3 < e) {
        uint4 v0 = base[(size_t)g_csr[i]   * 2 + l];
        uint4 v1 = base[(size_t)g_csr[i+1] * 2 + l];
        uint4 v2 = base[(size_t)g_csr[i+2] * 2 + l];
        uint4 v3 = base[(size_t)g_csr[i+3] * 2 + l];
        add8p(acc, v0, v1); add8p(acc, v2, v3);
        i += 4;
    }
    if (i + 1 < e) {
        add8p(acc, base[(size_t)g_csr[i] * 2 + l], base[(size_t)g_csr[i+1] * 2 + l]);
        i += 2;
    }
    if (i < e) add8(acc, base[(size_t)g_csr[i] * 2 + l]);

    int novf = g_novf2;                    // normally 0; correctness fallback
    for (int k = 0; k < novf; k++) {
        int2 p = g_ovf[k];
        if (p.x == nc) add8(acc, base[(size_t)p.y * 2 + l]);
    }

    float dv = g_dinv[nc];
    float z[8];
    #pragma unroll
    for (int k = 0; k < 8; k++) z[k] = fmaf(dv, acc[k], b2s[l * 8 + k]);

    float m = z[0];
    #pragma unroll
    for (int k = 1; k < 8; k++) m = fmaxf(m, z[k]);
    m = fmaxf(m, __shfl_xor_sync(0xffffffffu, m, 1));
    float sum = 0.f;
    #pragma unroll
    for (int k = 0; k < 8; k++) sum += __expf(z[k] - m);
    sum += __shfl_xor_sync(0xffffffffu, sum, 1);
    float lse = m + __logf(sum);

    if (node < N_NODES) {
        float4* outp = (float4*)out + (size_t)node * 4 + l * 2;
        float4 w0, w1;
        w0.x = z[0] - lse; w0.y = z[1] - lse; w0.z = z[2] - lse; w0.w = z[3] - lse;
        w1.x = z[4] - lse; w1.y = z[5] - lse; w1.z = z[6] - lse; w1.w = z[7] - lse;
        outp[0] = w0; outp[1] = w1;
    }
}

// ---------------- launch ------------------------------------------------------
extern "C" void kernel_launch(void* const* d_in, const int* in_sizes, int n_in,
                              void* d_out, int out_size) {
    const float* x  = (const float*)d_in[0];
    const void*  ei = d_in[1];
    const float* W1 = (const float*)d_in[2];
    const float* b1 = (const float*)d_in[3];
    const float* W2 = (const float*)d_in[4];
    const float* b2 = (const float*)d_in[5];
    float* out = (float*)d_out;

    int E = in_sizes[1] / 2;
    if (E > MAX_E) E = MAX_E;

    const int E2 = (E / 2 + 255) / 256;       // 2 edges/thread blocks

    k_fill<<<E2, 256>>>(ei, E);
    k_gemm1<<<N_NODES / 32, 256>>>(x, W1);
    k_gather1<<<(N_NODES + 63) / 64, 256>>>(b1, W2);
    k_gather2<<<(N_NODES + 127) / 128, 256>>>(b2, out);
}

// round 12
// speedup vs baseline: 1.4888x; 1.0286x over previous
#include <cuda_runtime.h>
#include <cuda_fp16.h>
#include <math.h>

#define N_NODES 100000
#define MAX_E   3200000
#define F_IN    128
#define F_HID   24
#define F_OUT   16
#define HID_PAD 32         // padded half-row stride for hs1 (64B lines)
#define CAP     64         // fixed bucket capacity per node (Poisson(32) max ~62)
#define PADI    32         // cursor stride in ints = 128B (kills LTS line serialization)

// ---------------- scratch (device globals; no allocation allowed) ------------
// Invariant: g_cursor is all-zero at kernel_launch entry (zero-init at load;
// k_gather2 re-zeroes after final read). g_novf reset by k_gemm1.
__device__ int    g_novf;
__device__ int    g_novf2;
__device__ int    g_cursor[N_NODES * PADI];   // 12.8MB, one counter per 128B line
__device__ float  g_dinv[N_NODES];
__device__ int    g_csr[N_NODES * CAP];       // 25.6MB fixed buckets
__device__ int2   g_ovf[MAX_E];               // overflow (dst,src); worst-case sized
__device__ __half g_hs1h[N_NODES * HID_PAD];  // (x@W1)*dinv, fp16, 64B rows
__device__ __half g_hs2h[N_NODES * F_OUT];    // (relu-l1 @ W2)*dinv, fp16, 32B rows

// dtype probe: int64 node ids < 2^31 -> odd 32-bit words all zero.
__device__ __forceinline__ int probe_is64(const void* ei) {
    const unsigned int* w = (const unsigned int*)ei;
    unsigned acc = 0;
    #pragma unroll
    for (int i = 0; i < 16; i++) acc |= w[2 * i + 1];
    return acc == 0u;
}

__device__ __forceinline__ int edge_at(const void* ei, int is64, long long idx) {
    return is64 ? (int)((const long long*)ei)[idx] : ((const int*)ei)[idx];
}

__device__ __forceinline__ void bucket_put(int dst, int src) {
    int c = atomicAdd(&g_cursor[dst * PADI], 1);
    if (c < CAP) g_csr[(dst << 6) + c] = src;
    else { int o = atomicAdd(&g_novf, 1); g_ovf[o] = make_int2(dst, src); }
}

// ---------------- single-pass bucket fill: 4 edges/thread, vectorized --------
__global__ void k_fill(const void* __restrict__ ei, int E) {
    __shared__ int sIs64;
    if (threadIdx.x == 0) sIs64 = probe_is64(ei);
    __syncthreads();
    int is64 = sIs64;
    int t = blockIdx.x * blockDim.x + threadIdx.x;
    int e = t * 4;
    if (e >= E) return;
    // vector path needs src-block 16B alignment: int64 -> E even, int32 -> E%4==0
    int vec_ok = is64 ? ((E & 1) == 0) : ((E & 3) == 0);
    if (vec_ok && e + 3 < E) {
        int d0, d1, d2, d3, s0, s1, s2, s3;
        if (is64) {
            longlong2 da = ((const longlong2*)ei)[t * 2];
            longlong2 db = ((const longlong2*)ei)[t * 2 + 1];
            longlong2 sa = ((const longlong2*)ei)[(E >> 1) + t * 2];
            longlong2 sb = ((const longlong2*)ei)[(E >> 1) + t * 2 + 1];
            d0 = (int)da.x; d1 = (int)da.y; d2 = (int)db.x; d3 = (int)db.y;
            s0 = (int)sa.x; s1 = (int)sa.y; s2 = (int)sb.x; s3 = (int)sb.y;
        } else {
            int4 dv = ((const int4*)ei)[t];
            int4 sv = ((const int4*)ei)[(E >> 2) + t];
            d0 = dv.x; d1 = dv.y; d2 = dv.z; d3 = dv.w;
            s0 = sv.x; s1 = sv.y; s2 = sv.z; s3 = sv.w;
        }
        bucket_put(d0, s0); bucket_put(d1, s1);
        bucket_put(d2, s2); bucket_put(d3, s3);
    } else {
        int lim = e + 4; if (lim > E) lim = E;
        for (int j = e; j < lim; j++) {
            int dst = edge_at(ei, is64, j);
            int src = edge_at(ei, is64, (long long)E + j);
            bucket_put(dst, src);
        }
    }
}

// ---------------- GEMM1: hs1h = fp16((x @ W1) * dinv); computes dinv ---------
// Also latches g_novf -> g_novf2 and resets g_novf (single thread; runs after
// k_fill, before the gathers, so ordering is by kernel boundaries).
__global__ __launch_bounds__(256) void k_gemm1(const float* __restrict__ x,
                                               const float* __restrict__ W1) {
    __shared__ float Ws[F_IN * F_HID];                   // 12 KB
    __shared__ __align__(16) float xs[32 * F_IN];        // 16 KB
    int tid = threadIdx.x;
    if (blockIdx.x == 0 && tid == 0) {
        g_novf2 = g_novf;
        g_novf = 0;
    }
    for (int i = tid; i < F_IN * F_HID; i += 256) Ws[i] = W1[i];

    int base = blockIdx.x * 32;                          // 3125 * 32 = 100000
    const float4* xv = (const float4*)(x + (size_t)base * F_IN);
    float4* xsv = (float4*)xs;
    for (int i = tid; i < 32 * (F_IN / 4); i += 256) xsv[i] = xv[i];
    __syncthreads();

    int nloc = tid >> 3;                                 // 0..31
    int l = tid & 7;                                     // 0..7, 3 outputs each
    int node = base + nloc;

    float a0 = 0.f, a1 = 0.f, a2 = 0.f;
    const float* xr = xs + nloc * F_IN;
    #pragma unroll
    for (int k = 0; k < F_IN; k++) {
        float xk = xr[k];
        a0 = fmaf(xk, Ws[k * F_HID + l * 3 + 0], a0);
        a1 = fmaf(xk, Ws[k * F_HID + l * 3 + 1], a1);
        a2 = fmaf(xk, Ws[k * F_HID + l * 3 + 2], a2);
    }
    int deg = g_cursor[node * PADI];                     // total in-degree
    float dv = rsqrtf((float)(deg + 1));                 // +1 self-loop
    if (l == 0) g_dinv[node] = dv;
    __half* o = g_hs1h + (size_t)node * HID_PAD + l * 3;
    o[0] = __float2half_rn(a0 * dv);
    o[1] = __float2half_rn(a1 * dv);
    o[2] = __float2half_rn(a2 * dv);
    if (l == 7) {                                        // zero pad halfs [24..32)
        uint4 z = make_uint4(0u, 0u, 0u, 0u);
        *(uint4*)(g_hs1h + (size_t)node * HID_PAD + 24) = z;
    }
}

// fp32 accumulate of one fp16x8 vector
__device__ __forceinline__ void add8(float* acc, uint4 v) {
    __half2* hp = (__half2*)&v;
    #pragma unroll
    for (int c = 0; c < 4; c++) {
        float2 f = __half22float2(hp[c]);
        acc[2*c]   += f.x;
        acc[2*c+1] += f.y;
    }
}

// pairwise: fp16 add two vectors, convert pair-sum once, fp32 accumulate
__device__ __forceinline__ void add8p(float* acc, uint4 a, uint4 b) {
    __half2* pa = (__half2*)&a;
    __half2* pb = (__half2*)&b;
    #pragma unroll
    for (int c = 0; c < 4; c++) {
        float2 f = __half22float2(__hadd2(pa[c], pb[c]));
        acc[2*c]   += f.x;
        acc[2*c+1] += f.y;
    }
}

// ---------------- layer1 gather: 8 lanes/node (2 edge-halves) + relu + GEMM2 -
__global__ __launch_bounds__(256) void k_gather1(const float* __restrict__ b1,
                                                 const float* __restrict__ W2) {
    __shared__ float W2s[F_HID * F_OUT];
    __shared__ float b1s[F_HID];
    int tid = threadIdx.x;
    for (int i = tid; i < F_HID * F_OUT; i += 256) W2s[i] = W2[i];
    if (tid < F_HID) b1s[tid] = b1[tid];
    __syncthreads();

    int lane = tid & 31;
    int l = lane & 3;                      // uint4 slot within 64B row
    int half = (lane >> 2) & 1;            // which edge-half this sub-group owns
    int node = blockIdx.x * 32 + (tid >> 3);   // 3125 * 32 = 100000 exact

    const uint4* base = (const uint4*)g_hs1h;
    float acc[8];
    if (half == 0) {
        uint4 sv = base[(size_t)node * 4 + l];   // self-loop term
        __half2* hp = (__half2*)&sv;
        #pragma unroll
        for (int c = 0; c < 4; c++) {
            float2 f = __half22float2(hp[c]);
            acc[2*c] = f.x; acc[2*c+1] = f.y;
        }
    } else {
        #pragma unroll
        for (int k = 0; k < 8; k++) acc[k] = 0.f;
    }

    int cnt = g_cursor[node * PADI];
    int deg = cnt < CAP ? cnt : CAP;
    int d0 = (deg + 1) >> 1;               // edges in half 0
    int s = (node << 6) + (half ? d0 : 0);
    int e = (node << 6) + (half ? deg : d0);
    int i = s;
    for (; i + 7 < e; i += 8) {
        uint4 v0 = base[(size_t)g_csr[i]   * 4 + l];
        uint4 v1 = base[(size_t)g_csr[i+1] * 4 + l];
        uint4 v2 = base[(size_t)g_csr[i+2] * 4 + l];
        uint4 v3 = base[(size_t)g_csr[i+3] * 4 + l];
        uint4 v4 = base[(size_t)g_csr[i+4] * 4 + l];
        uint4 v5 = base[(size_t)g_csr[i+5] * 4 + l];
        uint4 v6 = base[(size_t)g_csr[i+6] * 4 + l];
        uint4 v7 = base[(size_t)g_csr[i+7] * 4 + l];
        add8p(acc, v0, v1); add8p(acc, v2, v3);
        add8p(acc, v4, v5); add8p(acc, v6, v7);
    }
    if (i + 3 < e) {
        uint4 v0 = base[(size_t)g_csr[i]   * 4 + l];
        uint4 v1 = base[(size_t)g_csr[i+1] * 4 + l];
        uint4 v2 = base[(size_t)g_csr[i+2] * 4 + l];
        uint4 v3 = base[(size_t)g_csr[i+3] * 4 + l];
        add8p(acc, v0, v1); add8p(acc, v2, v3);
        i += 4;
    }
    if (i + 1 < e) {
        add8p(acc, base[(size_t)g_csr[i] * 4 + l], base[(size_t)g_csr[i+1] * 4 + l]);
        i += 2;
    }
    if (i < e) add8(acc, base[(size_t)g_csr[i] * 4 + l]);

    if (half == 0) {                       // overflow fallback (normally 0)
        int novf = g_novf2;
        for (int k = 0; k < novf; k++) {
            int2 p = g_ovf[k];
            if (p.x == node) add8(acc, base[(size_t)p.y * 4 + l]);
        }
    }

    // combine the two halves (converged; full-warp shfl safe)
    #pragma unroll
    for (int k = 0; k < 8; k++)
        acc[k] += __shfl_xor_sync(0xffffffffu, acc[k], 4);

    float dv = g_dinv[node];
    float h[8];
    if (l < 3) {
        #pragma unroll
        for (int k = 0; k < 8; k++)
            h[k] = fmaxf(fmaf(dv, acc[k], b1s[l * 8 + k]), 0.f);
    } else {
        #pragma unroll
        for (int k = 0; k < 8; k++) h[k] = 0.f;
    }

    float o0 = 0.f, o1 = 0.f, o2 = 0.f, o3 = 0.f;
    int gbase = lane & ~3;                 // 4-lane subgroup within own half
    #pragma unroll
    for (int j = 0; j < F_HID; j++) {
        float hj = __shfl_sync(0xffffffffu, h[j & 7], gbase + (j >> 3));
        o0 = fmaf(hj, W2s[j * F_OUT + l*4 + 0], o0);
        o1 = fmaf(hj, W2s[j * F_OUT + l*4 + 1], o1);
        o2 = fmaf(hj, W2s[j * F_OUT + l*4 + 2], o2);
        o3 = fmaf(hj, W2s[j * F_OUT + l*4 + 3], o3);
    }
    if (half == 0) {
        __half2* op = (__half2*)(g_hs2h + (size_t)node * F_OUT + l * 4);
        op[0] = __floats2half2_rn(o0 * dv, o1 * dv);
        op[1] = __floats2half2_rn(o2 * dv, o3 * dv);
    }
}

// ---------------- layer2 gather: 4 lanes/node (2 edge-halves) + log_softmax --
// Also re-zeroes each node's cursor after the final read.
__global__ __launch_bounds__(256) void k_gather2(const float* __restrict__ b2,
                                                 float* __restrict__ out) {
    __shared__ float b2s[F_OUT];
    if (threadIdx.x < F_OUT) b2s[threadIdx.x] = b2[threadIdx.x];
    __syncthreads();

    int tid = threadIdx.x;
    int lane = tid & 31;
    int l = lane & 1;                      // uint4 slot within 32B row
    int half = (lane >> 1) & 1;
    int node = blockIdx.x * 64 + (tid >> 2);
    int nc = (node < N_NODES) ? node : (N_NODES - 1);

    const uint4* base = (const uint4*)g_hs2h;
    float acc[8];
    if (half == 0) {
        uint4 sv = base[(size_t)nc * 2 + l];     // self-loop term
        __half2* hp = (__half2*)&sv;
        #pragma unroll
        for (int c = 0; c < 4; c++) {
            float2 f = __half22float2(hp[c]);
            acc[2*c] = f.x; acc[2*c+1] = f.y;
        }
    } else {
        #pragma unroll
        for (int k = 0; k < 8; k++) acc[k] = 0.f;
    }

    int cnt = g_cursor[nc * PADI];
    if ((lane & 3) == 0 && node < N_NODES) g_cursor[nc * PADI] = 0;  // reset for next call
    int deg = cnt < CAP ? cnt : CAP;
    int d0 = (deg + 1) >> 1;
    int s = (nc << 6) + (half ? d0 : 0);
    int e = (nc << 6) + (half ? deg : d0);
    int i = s;
    for (; i + 7 < e; i += 8) {
        uint4 v0 = base[(size_t)g_csr[i]   * 2 + l];
        uint4 v1 = base[(size_t)g_csr[i+1] * 2 + l];
        uint4 v2 = base[(size_t)g_csr[i+2] * 2 + l];
        uint4 v3 = base[(size_t)g_csr[i+3] * 2 + l];
        uint4 v4 = base[(size_t)g_csr[i+4] * 2 + l];
        uint4 v5 = base[(size_t)g_csr[i+5] * 2 + l];
        uint4 v6 = base[(size_t)g_csr[i+6] * 2 + l];
        uint4 v7 = base[(size_t)g_csr[i+7] * 2 + l];
        add8p(acc, v0, v1); add8p(acc, v2, v3);
        add8p(acc, v4, v5); add8p(acc, v6, v7);
    }
    if (i + 3 < e) {
        uint4 v0 = base[(size_t)g_csr[i]   * 2 + l];
        uint4 v1 = base[(size_t)g_csr[i+1] * 2 + l];
        uint4 v2 = base[(size_t)g_csr[i+2] * 2 + l];
        uint4 v3 = base[(size_t)g_csr[i+3] * 2 + l];
        add8p(acc, v0, v1); add8p(acc, v2, v3);
        i += 4;
    }
    if (i + 1 < e) {
        add8p(acc, base[(size_t)g_csr[i] * 2 + l], base[(size_t)g_csr[i+1] * 2 + l]);
        i += 2;
    }
    if (i < e) add8(acc, base[(size_t)g_csr[i] * 2 + l]);

    if (half == 0) {                       // overflow fallback (normally 0)
        int novf = g_novf2;
        for (int k = 0; k < novf; k++) {
            int2 p = g_ovf[k];
            if (p.x == nc) add8(acc, base[(size_t)p.y * 2 + l]);
        }
    }

    // combine halves (converged; full-warp shfl safe)
    #pragma unroll
    for (int k = 0; k < 8; k++)
        acc[k] += __shfl_xor_sync(0xffffffffu, acc[k], 2);

    float dv = g_dinv[nc];
    float z[8];
    #pragma unroll
    for (int k = 0; k < 8; k++) z[k] = fmaf(dv, acc[k], b2s[l * 8 + k]);

    float m = z[0];
    #pragma unroll
    for (int k = 1; k < 8; k++) m = fmaxf(m, z[k]);
    m = fmaxf(m, __shfl_xor_sync(0xffffffffu, m, 1));
    float sum = 0.f;
    #pragma unroll
    for (int k = 0; k < 8; k++) sum += __expf(z[k] - m);
    sum += __shfl_xor_sync(0xffffffffu, sum, 1);
    float lse = m + __logf(sum);

    if (node < N_NODES && half == 0) {
        float4* outp = (float4*)out + (size_t)node * 4 + l * 2;
        float4 w0, w1;
        w0.x = z[0] - lse; w0.y = z[1] - lse; w0.z = z[2] - lse; w0.w = z[3] - lse;
        w1.x = z[4] - lse; w1.y = z[5] - lse; w1.z = z[6] - lse; w1.w = z[7] - lse;
        outp[0] = w0; outp[1] = w1;
    }
}

// ---------------- launch ------------------------------------------------------
extern "C" void kernel_launch(void* const* d_in, const int* in_sizes, int n_in,
                              void* d_out, int out_size) {
    const float* x  = (const float*)d_in[0];
    const void*  ei = d_in[1];
    const float* W1 = (const float*)d_in[2];
    const float* b1 = (const float*)d_in[3];
    const float* W2 = (const float*)d_in[4];
    const float* b2 = (const float*)d_in[5];
    float* out = (float*)d_out;

    int E = in_sizes[1] / 2;
    if (E > MAX_E) E = MAX_E;

    const int E4 = (E / 4 + 255) / 256 + 1;   // 4 edges/thread blocks

    k_fill<<<E4, 256>>>(ei, E);
    k_gemm1<<<N_NODES / 32, 256>>>(x, W1);
    k_gather1<<<N_NODES / 32, 256>>>(b1, W2);
    k_gather2<<<(N_NODES + 63) / 64, 256>>>(b2, out);
}